// round 3
// baseline (speedup 1.0000x reference)
#include <cuda_runtime.h>
#include <math.h>

// Problem constants (fixed by the dataset)
#define NN 100000
#define EE 1600000

// Scratch (allocation-free rule: static __device__ globals).
// 256B alignment: we use 128-bit vector red/store on these.
__device__ __align__(256) float g_dinv[NN];
__device__ __align__(256) float g_buf1[NN * 128];
__device__ __align__(256) float g_buf2[NN * 128];
__device__ __align__(256) float g_w[EE];

// ---------------------------------------------------------------------------
// degree / edge preprocessing  (edge_index is int32: JAX default x64-disabled)
// ---------------------------------------------------------------------------
__global__ void deg_init(float* deg, int n) {
    int i = blockIdx.x * blockDim.x + threadIdx.x;
    if (i < n) deg[i] = 1.0f;   // self loop
}

__global__ void deg_scatter(const int* __restrict__ dst, float* deg, int E) {
    int i = blockIdx.x * blockDim.x + threadIdx.x;
    if (i < E) atomicAdd(&deg[dst[i]], 1.0f);
}

__global__ void deg_finish(float* deg, int n) {
    int i = blockIdx.x * blockDim.x + threadIdx.x;
    if (i < n) deg[i] = rsqrtf(deg[i]);
}

__global__ void edge_prep(const int* __restrict__ src,
                          const int* __restrict__ dst,
                          const float* __restrict__ dinv,
                          float* __restrict__ w, int E) {
    int i = blockIdx.x * blockDim.x + threadIdx.x;
    if (i >= E) return;
    w[i] = dinv[src[i]] * dinv[dst[i]];
}

// ---------------------------------------------------------------------------
// GEMM: out[M, Nout] = concat(xA[:,0:KA], xB[:,0:KB]) @ W[K, Nout]
// Classic register-tiled SGEMM. KA, KB, Nout multiples of 4; K % BK == 0.
// ---------------------------------------------------------------------------
template <int BM, int BN, int BK, int TM, int TN>
__global__ void gemm_concat(const float* __restrict__ xA, int KA,
                            const float* __restrict__ xB, int KB,
                            const float* __restrict__ W,
                            float* __restrict__ out, int M, int Nout) {
    const int K = KA + KB;
    __shared__ float Xs[BK][BM];
    __shared__ float Ws[BK][BN];

    constexpr int THREADS = (BM / TM) * (BN / TN);
    const int tid = threadIdx.x;
    const int rowBase = blockIdx.y * BM;
    const int colBase = blockIdx.x * BN;

    const int tn = tid % (BN / TN);
    const int tm = tid / (BN / TN);

    float acc[TM][TN];
#pragma unroll
    for (int i = 0; i < TM; i++)
#pragma unroll
        for (int j = 0; j < TN; j++) acc[i][j] = 0.0f;

    for (int k0 = 0; k0 < K; k0 += BK) {
        // ---- load X tile (BM x BK), float4 along K, store transposed ----
        constexpr int XV = BM * BK / 4;
        for (int idx = tid; idx < XV; idx += THREADS) {
            int r = idx / (BK / 4);
            int kq = idx % (BK / 4);
            int gr = rowBase + r;
            int k = k0 + kq * 4;
            float4 v = make_float4(0.f, 0.f, 0.f, 0.f);
            if (gr < M) {
                const float* p = (k < KA)
                    ? (xA + (size_t)gr * KA + k)
                    : (xB + (size_t)gr * KB + (k - KA));
                v = *(const float4*)p;
            }
            Xs[kq * 4 + 0][r] = v.x;
            Xs[kq * 4 + 1][r] = v.y;
            Xs[kq * 4 + 2][r] = v.z;
            Xs[kq * 4 + 3][r] = v.w;
        }
        // ---- load W tile (BK x BN) ----
        constexpr int WV = BK * BN / 4;
        for (int idx = tid; idx < WV; idx += THREADS) {
            int kr = idx / (BN / 4);
            int nc = idx % (BN / 4);
            float4 v = *(const float4*)(W + (size_t)(k0 + kr) * Nout + colBase + nc * 4);
            *(float4*)&Ws[kr][nc * 4] = v;
        }
        __syncthreads();

#pragma unroll
        for (int k = 0; k < BK; k++) {
            float a[TM], b[TN];
#pragma unroll
            for (int i = 0; i < TM; i++) a[i] = Xs[k][tm * TM + i];
#pragma unroll
            for (int j = 0; j < TN; j++) b[j] = Ws[k][tn * TN + j];
#pragma unroll
            for (int i = 0; i < TM; i++)
#pragma unroll
                for (int j = 0; j < TN; j++) acc[i][j] = fmaf(a[i], b[j], acc[i][j]);
        }
        __syncthreads();
    }

    // ---- store ----
#pragma unroll
    for (int i = 0; i < TM; i++) {
        int gr = rowBase + tm * TM + i;
        if (gr < M) {
            float* o = out + (size_t)gr * Nout + colBase + tn * TN;
#pragma unroll
            for (int j = 0; j < TN; j += 4) {
                float4 v = make_float4(acc[i][j], acc[i][j + 1], acc[i][j + 2], acc[i][j + 3]);
                *(float4*)(o + j) = v;
            }
        }
    }
}

// ---------------------------------------------------------------------------
// Aggregation: out = D^-1/2 (A+I) D^-1/2 H
//   step 1: out[i] = H[i] * dinv[i]^2           (self term, full overwrite)
//   step 2: for each edge: out[dst] += H[src] * w[e]   (red.global.v4)
// ---------------------------------------------------------------------------
template <int F>
__global__ void self_init(const float* __restrict__ H, const float* __restrict__ dinv,
                          float* __restrict__ out, int M) {
    constexpr int C = F / 4;
    int t = blockIdx.x * blockDim.x + threadIdx.x;
    if (t >= M * C) return;
    int r = t / C;
    float s = dinv[r];
    s *= s;
    float4 v = ((const float4*)H)[t];
    v.x *= s; v.y *= s; v.z *= s; v.w *= s;
    ((float4*)out)[t] = v;
}

template <int F>
__global__ void edge_scatter(const float* __restrict__ H,
                             const int* __restrict__ src,
                             const int* __restrict__ dst,
                             const float* __restrict__ w,
                             float* __restrict__ out, int E) {
    constexpr int C = F / 4;   // float4 chunks per row
    int t = blockIdx.x * blockDim.x + threadIdx.x;
    if (t >= E * C) return;
    int e = t / C;
    int c = t - e * C;
    int s = src[e];
    int d = dst[e];
    float cw = w[e];
    float4 v = *(const float4*)(H + (size_t)s * F + c * 4);
    v.x *= cw; v.y *= cw; v.z *= cw; v.w *= cw;
    float* addr = out + (size_t)d * F + c * 4;
    asm volatile("red.global.add.v4.f32 [%0], {%1,%2,%3,%4};"
                 :: "l"(addr), "f"(v.x), "f"(v.y), "f"(v.z), "f"(v.w)
                 : "memory");
}

// out = (act ? tanh : id)(out + bias)
template <int F>
__global__ void epilogue(float* __restrict__ buf, const float* __restrict__ bias,
                         int M, int act) {
    constexpr int C = F / 4;
    int t = blockIdx.x * blockDim.x + threadIdx.x;
    if (t >= M * C) return;
    int c = t - (t / C) * C;
    float4 v = ((float4*)buf)[t];
    float4 b = ((const float4*)bias)[c];
    v.x += b.x; v.y += b.y; v.z += b.z; v.w += b.w;
    if (act) {
        v.x = tanhf(v.x); v.y = tanhf(v.y); v.z = tanhf(v.z); v.w = tanhf(v.w);
    }
    ((float4*)buf)[t] = v;
}

// ---------------------------------------------------------------------------
// Host side
// ---------------------------------------------------------------------------
static inline int cdiv(int a, int b) { return (a + b - 1) / b; }

template <int F>
static void aggregate(const float* H, const int* src, const int* dst,
                      const float* w, const float* dinv, float* out,
                      const float* bias, int M, int E, int act) {
    constexpr int C = F / 4;
    self_init<F><<<cdiv(M * C, 256), 256>>>(H, dinv, out, M);
    edge_scatter<F><<<cdiv(E * C, 256), 256>>>(H, src, dst, w, out, E);
    epilogue<F><<<cdiv(M * C, 256), 256>>>(out, bias, M, act);
}

extern "C" void kernel_launch(void* const* d_in, const int* in_sizes, int n_in,
                              void* d_out, int out_size) {
    const float* feat = (const float*)d_in[0];   // [N,128] f32
    const float* cond = (const float*)d_in[1];   // [N,32]  f32
    const int*   ei   = (const int*)d_in[2];     // [2,E] int32 (JAX x64 disabled)
    const float* We1 = (const float*)d_in[3];
    const float* be1 = (const float*)d_in[4];
    const float* We2 = (const float*)d_in[5];
    const float* be2 = (const float*)d_in[6];
    const float* We3 = (const float*)d_in[7];
    const float* be3 = (const float*)d_in[8];
    const float* Wd1 = (const float*)d_in[9];
    const float* bd1 = (const float*)d_in[10];
    const float* Wd2 = (const float*)d_in[11];
    const float* bd2 = (const float*)d_in[12];
    const float* Wd3 = (const float*)d_in[13];
    const float* bd3 = (const float*)d_in[14];

    const int N = in_sizes[0] / 128;
    const int E = in_sizes[2] / 2;
    const int* src = ei;
    const int* dst = ei + E;
    float* out = (float*)d_out;

    float *dinv, *buf1, *buf2, *w;
    cudaGetSymbolAddress((void**)&dinv, g_dinv);
    cudaGetSymbolAddress((void**)&buf1, g_buf1);
    cudaGetSymbolAddress((void**)&buf2, g_buf2);
    cudaGetSymbolAddress((void**)&w, g_w);

    // 1) degrees -> dinv, edge weights
    deg_init<<<cdiv(N, 256), 256>>>(dinv, N);
    deg_scatter<<<cdiv(E, 256), 256>>>(dst, dinv, E);
    deg_finish<<<cdiv(N, 256), 256>>>(dinv, N);
    edge_prep<<<cdiv(E, 256), 256>>>(src, dst, dinv, w, E);

    dim3 g128(1, cdiv(N, 128));

    // 2) encoder layer 1: [feat|cond] (K=160) -> 128, tanh
    gemm_concat<128, 128, 16, 8, 8><<<g128, 256>>>(feat, 128, cond, 32, We1, buf1, N, 128);
    aggregate<128>(buf1, src, dst, w, dinv, buf2, be1, N, E, 1);

    // 3) encoder layer 2: 128 -> 128, tanh
    gemm_concat<128, 128, 16, 8, 8><<<g128, 256>>>(buf2, 128, nullptr, 0, We2, buf1, N, 128);
    aggregate<128>(buf1, src, dst, w, dinv, buf2, be2, N, E, 1);

    // 4) encoder layer 3: 128 -> 64 (z), no activation
    gemm_concat<128, 64, 16, 8, 4><<<g128, 256>>>(buf2, 128, nullptr, 0, We3, buf1, N, 64);
    aggregate<64>(buf1, src, dst, w, dinv, buf2, be3, N, E, 0);  // buf2 = z [N,64]

    // 5) decoder layer 1: [z|cond] (K=96) -> 128, tanh
    gemm_concat<128, 128, 16, 8, 8><<<g128, 256>>>(buf2, 64, cond, 32, Wd1, buf1, N, 128);
    aggregate<128>(buf1, src, dst, w, dinv, buf2, bd1, N, E, 1);

    // 6) decoder layer 2: 128 -> 128, tanh
    gemm_concat<128, 128, 16, 8, 8><<<g128, 256>>>(buf2, 128, nullptr, 0, Wd2, buf1, N, 128);
    aggregate<128>(buf1, src, dst, w, dinv, buf2, bd2, N, E, 1);

    // 7) decoder layer 3: 128 -> 128, no activation, write to d_out
    gemm_concat<128, 128, 16, 8, 8><<<g128, 256>>>(buf2, 128, nullptr, 0, Wd3, buf1, N, 128);
    aggregate<128>(buf1, src, dst, w, dinv, out, bd3, N, E, 0);
}

// round 4
// speedup vs baseline: 1.7758x; 1.7758x over previous
#include <cuda_runtime.h>
#include <math.h>

// Problem constants (fixed by the dataset)
#define NN 100000
#define EE 1600000

// Scratch (allocation-free rule: static __device__ globals).
__device__ __align__(256) float g_dinv[NN];
__device__ __align__(256) int   g_deg[NN];
__device__ __align__(256) int   g_rowstart[NN];
__device__ __align__(256) int   g_cursor[NN];
__device__ __align__(256) int   g_csr_src[EE];
__device__ __align__(256) float g_csr_w[EE];
__device__ __align__(256) float g_buf1[NN * 128];
__device__ __align__(256) float g_buf2[NN * 128];
__device__ int g_gcur;   // global slice cursor (reset every launch)

static inline int cdiv(int a, int b) { return (a + b - 1) / b; }

// ---------------------------------------------------------------------------
// CSR construction (edge_index is int32)
// ---------------------------------------------------------------------------
__global__ void reset_counters(int* deg, int* gcur, int n) {
    int i = blockIdx.x * blockDim.x + threadIdx.x;
    if (i < n) deg[i] = 0;
    if (i == 0) *gcur = 0;
}

__global__ void deg_count(const int* __restrict__ dst, int* __restrict__ deg, int E) {
    int i = blockIdx.x * blockDim.x + threadIdx.x;
    if (i < E) atomicAdd(&deg[dst[i]], 1);
}

__global__ void dinv_compute(const int* __restrict__ deg, float* __restrict__ dinv, int n) {
    int i = blockIdx.x * blockDim.x + threadIdx.x;
    if (i < n) dinv[i] = rsqrtf((float)deg[i] + 1.0f);
}

// Assign each node a contiguous slice of the csr arrays.
// Warp-aggregated: one global atomicAdd per warp, lane offsets via warp scan.
__global__ void assign_rows(const int* __restrict__ deg, int* __restrict__ rowstart,
                            int* __restrict__ cursor, int* gcur, int n) {
    int i = blockIdx.x * blockDim.x + threadIdx.x;
    int lane = threadIdx.x & 31;
    int d = (i < n) ? deg[i] : 0;
    int incl = d;
#pragma unroll
    for (int o = 1; o < 32; o <<= 1) {
        int v = __shfl_up_sync(0xFFFFFFFFu, incl, o);
        if (lane >= o) incl += v;
    }
    int total = __shfl_sync(0xFFFFFFFFu, incl, 31);
    int base = 0;
    if (lane == 31) base = atomicAdd(gcur, total);
    base = __shfl_sync(0xFFFFFFFFu, base, 31);
    int excl = incl - d;
    if (i < n) {
        rowstart[i] = base + excl;
        cursor[i]   = base + excl;
    }
}

__global__ void csr_fill(const int* __restrict__ src, const int* __restrict__ dst,
                         const float* __restrict__ dinv,
                         int* __restrict__ cursor,
                         int* __restrict__ csr_src, float* __restrict__ csr_w, int E) {
    int i = blockIdx.x * blockDim.x + threadIdx.x;
    if (i >= E) return;
    int s = src[i];
    int d = dst[i];
    int pos = atomicAdd(&cursor[d], 1);
    csr_src[pos] = s;
    csr_w[pos] = dinv[s] * dinv[d];
}

// ---------------------------------------------------------------------------
// GEMM: out[M, Nout] = concat(xA[:,0:KA], xB[:,0:KB]) @ W[K, Nout]
// ---------------------------------------------------------------------------
template <int BM, int BN, int BK, int TM, int TN>
__global__ void gemm_concat(const float* __restrict__ xA, int KA,
                            const float* __restrict__ xB, int KB,
                            const float* __restrict__ W,
                            float* __restrict__ out, int M, int Nout) {
    const int K = KA + KB;
    __shared__ float Xs[BK][BM];
    __shared__ float Ws[BK][BN];

    constexpr int THREADS = (BM / TM) * (BN / TN);
    const int tid = threadIdx.x;
    const int rowBase = blockIdx.y * BM;
    const int colBase = blockIdx.x * BN;

    const int tn = tid % (BN / TN);
    const int tm = tid / (BN / TN);

    float acc[TM][TN];
#pragma unroll
    for (int i = 0; i < TM; i++)
#pragma unroll
        for (int j = 0; j < TN; j++) acc[i][j] = 0.0f;

    for (int k0 = 0; k0 < K; k0 += BK) {
        constexpr int XV = BM * BK / 4;
        for (int idx = tid; idx < XV; idx += THREADS) {
            int r = idx / (BK / 4);
            int kq = idx % (BK / 4);
            int gr = rowBase + r;
            int k = k0 + kq * 4;
            float4 v = make_float4(0.f, 0.f, 0.f, 0.f);
            if (gr < M) {
                const float* p = (k < KA)
                    ? (xA + (size_t)gr * KA + k)
                    : (xB + (size_t)gr * KB + (k - KA));
                v = *(const float4*)p;
            }
            Xs[kq * 4 + 0][r] = v.x;
            Xs[kq * 4 + 1][r] = v.y;
            Xs[kq * 4 + 2][r] = v.z;
            Xs[kq * 4 + 3][r] = v.w;
        }
        constexpr int WV = BK * BN / 4;
        for (int idx = tid; idx < WV; idx += THREADS) {
            int kr = idx / (BN / 4);
            int nc = idx % (BN / 4);
            float4 v = *(const float4*)(W + (size_t)(k0 + kr) * Nout + colBase + nc * 4);
            *(float4*)&Ws[kr][nc * 4] = v;
        }
        __syncthreads();

#pragma unroll
        for (int k = 0; k < BK; k++) {
            float a[TM], b[TN];
#pragma unroll
            for (int i = 0; i < TM; i++) a[i] = Xs[k][tm * TM + i];
#pragma unroll
            for (int j = 0; j < TN; j++) b[j] = Ws[k][tn * TN + j];
#pragma unroll
            for (int i = 0; i < TM; i++)
#pragma unroll
                for (int j = 0; j < TN; j++) acc[i][j] = fmaf(a[i], b[j], acc[i][j]);
        }
        __syncthreads();
    }

#pragma unroll
    for (int i = 0; i < TM; i++) {
        int gr = rowBase + tm * TM + i;
        if (gr < M) {
            float* o = out + (size_t)gr * Nout + colBase + tn * TN;
#pragma unroll
            for (int j = 0; j < TN; j += 4) {
                float4 v = make_float4(acc[i][j], acc[i][j + 1], acc[i][j + 2], acc[i][j + 3]);
                *(float4*)(o + j) = v;
            }
        }
    }
}

// ---------------------------------------------------------------------------
// Fused aggregation: out[d] = act( dinv[d]^2*H[d] + sum_e w[e]*H[src[e]] + b )
// One warp per node. F=128 -> float4/lane, F=64 -> float2/lane. No atomics.
// ---------------------------------------------------------------------------
template <int F, int ACT>
__global__ void agg_fused(const float* __restrict__ H,
                          const int* __restrict__ rowstart,
                          const int* __restrict__ deg,
                          const int* __restrict__ csr_src,
                          const float* __restrict__ csr_w,
                          const float* __restrict__ dinv,
                          const float* __restrict__ bias,
                          float* __restrict__ out, int M) {
    constexpr int V = F / 32;          // floats per lane (4 or 2)
    int warp = (blockIdx.x * blockDim.x + threadIdx.x) >> 5;
    if (warp >= M) return;
    int lane = threadIdx.x & 31;

    float acc[V];
    // self-loop term
    {
        float dv = dinv[warp];
        float s = dv * dv;
        if (V == 4) {
            float4 v = *(const float4*)(H + (size_t)warp * F + lane * 4);
            acc[0] = s * v.x; acc[1] = s * v.y; acc[2] = s * v.z; acc[3] = s * v.w;
        } else {
            float2 v = *(const float2*)(H + (size_t)warp * F + lane * 2);
            acc[0] = s * v.x; acc[1] = s * v.y;
        }
    }

    int beg = rowstart[warp];
    int n = deg[warp];
    int j = 0;
    // 2-way unroll for MLP
    for (; j + 2 <= n; j += 2) {
        int s0 = csr_src[beg + j];
        int s1 = csr_src[beg + j + 1];
        float w0 = csr_w[beg + j];
        float w1 = csr_w[beg + j + 1];
        if (V == 4) {
            float4 v0 = *(const float4*)(H + (size_t)s0 * F + lane * 4);
            float4 v1 = *(const float4*)(H + (size_t)s1 * F + lane * 4);
            acc[0] = fmaf(w0, v0.x, acc[0]); acc[1] = fmaf(w0, v0.y, acc[1]);
            acc[2] = fmaf(w0, v0.z, acc[2]); acc[3] = fmaf(w0, v0.w, acc[3]);
            acc[0] = fmaf(w1, v1.x, acc[0]); acc[1] = fmaf(w1, v1.y, acc[1]);
            acc[2] = fmaf(w1, v1.z, acc[2]); acc[3] = fmaf(w1, v1.w, acc[3]);
        } else {
            float2 v0 = *(const float2*)(H + (size_t)s0 * F + lane * 2);
            float2 v1 = *(const float2*)(H + (size_t)s1 * F + lane * 2);
            acc[0] = fmaf(w0, v0.x, acc[0]); acc[1] = fmaf(w0, v0.y, acc[1]);
            acc[0] = fmaf(w1, v1.x, acc[0]); acc[1] = fmaf(w1, v1.y, acc[1]);
        }
    }
    if (j < n) {
        int s0 = csr_src[beg + j];
        float w0 = csr_w[beg + j];
        if (V == 4) {
            float4 v0 = *(const float4*)(H + (size_t)s0 * F + lane * 4);
            acc[0] = fmaf(w0, v0.x, acc[0]); acc[1] = fmaf(w0, v0.y, acc[1]);
            acc[2] = fmaf(w0, v0.z, acc[2]); acc[3] = fmaf(w0, v0.w, acc[3]);
        } else {
            float2 v0 = *(const float2*)(H + (size_t)s0 * F + lane * 2);
            acc[0] = fmaf(w0, v0.x, acc[0]); acc[1] = fmaf(w0, v0.y, acc[1]);
        }
    }

    // bias + activation + store
    if (V == 4) {
        float4 b = *(const float4*)(bias + lane * 4);
        acc[0] += b.x; acc[1] += b.y; acc[2] += b.z; acc[3] += b.w;
        if (ACT) {
            acc[0] = tanhf(acc[0]); acc[1] = tanhf(acc[1]);
            acc[2] = tanhf(acc[2]); acc[3] = tanhf(acc[3]);
        }
        float4 o = make_float4(acc[0], acc[1], acc[2], acc[3]);
        *(float4*)(out + (size_t)warp * F + lane * 4) = o;
    } else {
        float2 b = *(const float2*)(bias + lane * 2);
        acc[0] += b.x; acc[1] += b.y;
        if (ACT) { acc[0] = tanhf(acc[0]); acc[1] = tanhf(acc[1]); }
        float2 o = make_float2(acc[0], acc[1]);
        *(float2*)(out + (size_t)warp * F + lane * 2) = o;
    }
}

// ---------------------------------------------------------------------------
// Host side
// ---------------------------------------------------------------------------
extern "C" void kernel_launch(void* const* d_in, const int* in_sizes, int n_in,
                              void* d_out, int out_size) {
    const float* feat = (const float*)d_in[0];   // [N,128] f32
    const float* cond = (const float*)d_in[1];   // [N,32]  f32
    const int*   ei   = (const int*)d_in[2];     // [2,E] int32
    const float* We1 = (const float*)d_in[3];
    const float* be1 = (const float*)d_in[4];
    const float* We2 = (const float*)d_in[5];
    const float* be2 = (const float*)d_in[6];
    const float* We3 = (const float*)d_in[7];
    const float* be3 = (const float*)d_in[8];
    const float* Wd1 = (const float*)d_in[9];
    const float* bd1 = (const float*)d_in[10];
    const float* Wd2 = (const float*)d_in[11];
    const float* bd2 = (const float*)d_in[12];
    const float* Wd3 = (const float*)d_in[13];
    const float* bd3 = (const float*)d_in[14];

    const int N = in_sizes[0] / 128;
    const int E = in_sizes[2] / 2;
    const int* src = ei;
    const int* dst = ei + E;
    float* out = (float*)d_out;

    float *dinv, *buf1, *buf2, *csr_w;
    int *deg, *rowstart, *cursor, *csr_src, *gcur;
    cudaGetSymbolAddress((void**)&dinv, g_dinv);
    cudaGetSymbolAddress((void**)&deg, g_deg);
    cudaGetSymbolAddress((void**)&rowstart, g_rowstart);
    cudaGetSymbolAddress((void**)&cursor, g_cursor);
    cudaGetSymbolAddress((void**)&csr_src, g_csr_src);
    cudaGetSymbolAddress((void**)&csr_w, g_csr_w);
    cudaGetSymbolAddress((void**)&buf1, g_buf1);
    cudaGetSymbolAddress((void**)&buf2, g_buf2);
    cudaGetSymbolAddress((void**)&gcur, g_gcur);

    // ---- CSR build (once per launch) ----
    reset_counters<<<cdiv(N, 256), 256>>>(deg, gcur, N);
    deg_count<<<cdiv(E, 256), 256>>>(dst, deg, E);
    dinv_compute<<<cdiv(N, 256), 256>>>(deg, dinv, N);
    assign_rows<<<cdiv(N, 256), 256>>>(deg, rowstart, cursor, gcur, N);
    csr_fill<<<cdiv(E, 256), 256>>>(src, dst, dinv, cursor, csr_src, csr_w, E);

    dim3 g128(1, cdiv(N, 128));
    const int aggBlocks128 = cdiv(N * 32, 256);

    // encoder layer 1: [feat|cond] (K=160) -> 128, tanh
    gemm_concat<128, 128, 16, 8, 8><<<g128, 256>>>(feat, 128, cond, 32, We1, buf1, N, 128);
    agg_fused<128, 1><<<aggBlocks128, 256>>>(buf1, rowstart, deg, csr_src, csr_w, dinv, be1, buf2, N);

    // encoder layer 2: 128 -> 128, tanh
    gemm_concat<128, 128, 16, 8, 8><<<g128, 256>>>(buf2, 128, nullptr, 0, We2, buf1, N, 128);
    agg_fused<128, 1><<<aggBlocks128, 256>>>(buf1, rowstart, deg, csr_src, csr_w, dinv, be2, buf2, N);

    // encoder layer 3: 128 -> 64 (z), no activation
    gemm_concat<128, 64, 16, 8, 4><<<g128, 256>>>(buf2, 128, nullptr, 0, We3, buf1, N, 64);
    agg_fused<64, 0><<<aggBlocks128, 256>>>(buf1, rowstart, deg, csr_src, csr_w, dinv, be3, buf2, N);

    // decoder layer 1: [z|cond] (K=96) -> 128, tanh
    gemm_concat<128, 128, 16, 8, 8><<<g128, 256>>>(buf2, 64, cond, 32, Wd1, buf1, N, 128);
    agg_fused<128, 1><<<aggBlocks128, 256>>>(buf1, rowstart, deg, csr_src, csr_w, dinv, bd1, buf2, N);

    // decoder layer 2: 128 -> 128, tanh
    gemm_concat<128, 128, 16, 8, 8><<<g128, 256>>>(buf2, 128, nullptr, 0, Wd2, buf1, N, 128);
    agg_fused<128, 1><<<aggBlocks128, 256>>>(buf1, rowstart, deg, csr_src, csr_w, dinv, bd2, buf2, N);

    // decoder layer 3: 128 -> 128, no activation, write to d_out
    gemm_concat<128, 128, 16, 8, 8><<<g128, 256>>>(buf2, 128, nullptr, 0, Wd3, buf1, N, 128);
    agg_fused<128, 0><<<aggBlocks128, 256>>>(buf1, rowstart, deg, csr_src, csr_w, dinv, bd3, out, N);
}

// round 5
// speedup vs baseline: 1.7884x; 1.0071x over previous
#include <cuda_runtime.h>
#include <math.h>

// Problem constants (fixed by the dataset)
#define NN 100000
#define EE 1600000

// Scratch (allocation-free rule: static __device__ globals).
__device__ __align__(256) float g_dinv[NN];
__device__ __align__(256) int   g_deg[NN];
__device__ __align__(256) int   g_rowstart[NN];
__device__ __align__(256) int   g_cursor[NN];
__device__ __align__(256) int   g_csr_src[EE];
__device__ __align__(256) float g_csr_w[EE];
__device__ __align__(256) float g_buf1[NN * 128];
__device__ __align__(256) float g_buf2[NN * 128];
__device__ int g_gcur;   // global slice cursor (reset every launch)

static inline int cdiv(int a, int b) { return (a + b - 1) / b; }

// ---------------------------------------------------------------------------
// packed f32x2 helpers (sm_103a FFMA2 pipe — only reachable via PTX f32x2)
// ---------------------------------------------------------------------------
__device__ __forceinline__ void ffma2(unsigned long long& d,
                                      unsigned long long a,
                                      unsigned long long b) {
    asm("fma.rn.f32x2 %0, %1, %2, %0;" : "+l"(d) : "l"(a), "l"(b));
}
__device__ __forceinline__ unsigned long long pack2(float lo, float hi) {
    unsigned long long r;
    asm("mov.b64 %0, {%1, %2};" : "=l"(r) : "f"(lo), "f"(hi));
    return r;
}
__device__ __forceinline__ void unpack2(unsigned long long p, float& lo, float& hi) {
    asm("mov.b64 {%0, %1}, %2;" : "=f"(lo), "=f"(hi) : "l"(p));
}

// ---------------------------------------------------------------------------
// CSR construction (edge_index is int32)
// ---------------------------------------------------------------------------
__global__ void reset_counters(int* deg, int* gcur, int n) {
    int i = blockIdx.x * blockDim.x + threadIdx.x;
    if (i < n) deg[i] = 0;
    if (i == 0) *gcur = 0;
}

__global__ void deg_count(const int* __restrict__ dst, int* __restrict__ deg, int E) {
    int i = blockIdx.x * blockDim.x + threadIdx.x;
    if (i < E) atomicAdd(&deg[dst[i]], 1);
}

__global__ void dinv_compute(const int* __restrict__ deg, float* __restrict__ dinv, int n) {
    int i = blockIdx.x * blockDim.x + threadIdx.x;
    if (i < n) dinv[i] = rsqrtf((float)deg[i] + 1.0f);
}

// Assign each node a contiguous slice of the csr arrays (warp-aggregated scan).
__global__ void assign_rows(const int* __restrict__ deg, int* __restrict__ rowstart,
                            int* __restrict__ cursor, int* gcur, int n) {
    int i = blockIdx.x * blockDim.x + threadIdx.x;
    int lane = threadIdx.x & 31;
    int d = (i < n) ? deg[i] : 0;
    int incl = d;
#pragma unroll
    for (int o = 1; o < 32; o <<= 1) {
        int v = __shfl_up_sync(0xFFFFFFFFu, incl, o);
        if (lane >= o) incl += v;
    }
    int total = __shfl_sync(0xFFFFFFFFu, incl, 31);
    int base = 0;
    if (lane == 31) base = atomicAdd(gcur, total);
    base = __shfl_sync(0xFFFFFFFFu, base, 31);
    int excl = incl - d;
    if (i < n) {
        rowstart[i] = base + excl;
        cursor[i]   = base + excl;
    }
}

__global__ void csr_fill(const int* __restrict__ src, const int* __restrict__ dst,
                         const float* __restrict__ dinv,
                         int* __restrict__ cursor,
                         int* __restrict__ csr_src, float* __restrict__ csr_w, int E) {
    int i = blockIdx.x * blockDim.x + threadIdx.x;
    if (i >= E) return;
    int s = src[i];
    int d = dst[i];
    int pos = atomicAdd(&cursor[d], 1);
    csr_src[pos] = s;
    csr_w[pos] = dinv[s] * dinv[d];
}

// ---------------------------------------------------------------------------
// GEMM: out[M, Nout] = concat(xA[:,0:KA], xB[:,0:KB]) @ W[K, Nout]
// Register-tiled, packed f32x2 inner loop (FFMA2).
// ---------------------------------------------------------------------------
template <int BM, int BN, int BK, int TM, int TN>
__global__ void gemm_concat(const float* __restrict__ xA, int KA,
                            const float* __restrict__ xB, int KB,
                            const float* __restrict__ W,
                            float* __restrict__ out, int M, int Nout) {
    static_assert(TN % 4 == 0 && TM % 4 == 0, "");
    const int K = KA + KB;
    __shared__ float Xs[BK][BM];
    __shared__ float Ws[BK][BN];

    constexpr int THREADS = (BM / TM) * (BN / TN);
    constexpr int TN2 = TN / 2;
    const int tid = threadIdx.x;
    const int rowBase = blockIdx.y * BM;
    const int colBase = blockIdx.x * BN;

    const int tn = tid % (BN / TN);
    const int tm = tid / (BN / TN);

    unsigned long long acc[TM][TN2];
#pragma unroll
    for (int i = 0; i < TM; i++)
#pragma unroll
        for (int j = 0; j < TN2; j++) acc[i][j] = 0ULL;

    for (int k0 = 0; k0 < K; k0 += BK) {
        // ---- load X tile (BM x BK), float4 along K, store transposed ----
        constexpr int XV = BM * BK / 4;
        for (int idx = tid; idx < XV; idx += THREADS) {
            int r = idx / (BK / 4);
            int kq = idx % (BK / 4);
            int gr = rowBase + r;
            int k = k0 + kq * 4;
            float4 v = make_float4(0.f, 0.f, 0.f, 0.f);
            if (gr < M) {
                const float* p = (k < KA)
                    ? (xA + (size_t)gr * KA + k)
                    : (xB + (size_t)gr * KB + (k - KA));
                v = *(const float4*)p;
            }
            Xs[kq * 4 + 0][r] = v.x;
            Xs[kq * 4 + 1][r] = v.y;
            Xs[kq * 4 + 2][r] = v.z;
            Xs[kq * 4 + 3][r] = v.w;
        }
        // ---- load W tile (BK x BN) ----
        constexpr int WV = BK * BN / 4;
        for (int idx = tid; idx < WV; idx += THREADS) {
            int kr = idx / (BN / 4);
            int nc = idx % (BN / 4);
            float4 v = *(const float4*)(W + (size_t)(k0 + kr) * Nout + colBase + nc * 4);
            *(float4*)&Ws[kr][nc * 4] = v;
        }
        __syncthreads();

#pragma unroll
        for (int k = 0; k < BK; k++) {
            // A fragment: TM floats -> packed broadcasts
            float a[TM];
#pragma unroll
            for (int i = 0; i < TM; i += 4) {
                float4 v = *(const float4*)&Xs[k][tm * TM + i];
                a[i + 0] = v.x; a[i + 1] = v.y; a[i + 2] = v.z; a[i + 3] = v.w;
            }
            unsigned long long a2[TM];
#pragma unroll
            for (int i = 0; i < TM; i++) a2[i] = pack2(a[i], a[i]);
            // B fragment: TN floats as TN/2 packed pairs
            unsigned long long b2[TN2];
            const unsigned long long* bp = (const unsigned long long*)&Ws[k][tn * TN];
#pragma unroll
            for (int j = 0; j < TN2; j++) b2[j] = bp[j];
#pragma unroll
            for (int i = 0; i < TM; i++)
#pragma unroll
                for (int j = 0; j < TN2; j++) ffma2(acc[i][j], a2[i], b2[j]);
        }
        __syncthreads();
    }

    // ---- store ----
#pragma unroll
    for (int i = 0; i < TM; i++) {
        int gr = rowBase + tm * TM + i;
        if (gr < M) {
            float* o = out + (size_t)gr * Nout + colBase + tn * TN;
#pragma unroll
            for (int j = 0; j < TN2; j += 2) {
                float4 v;
                unpack2(acc[i][j], v.x, v.y);
                unpack2(acc[i][j + 1], v.z, v.w);
                *(float4*)(o + j * 2) = v;
            }
        }
    }
}

// ---------------------------------------------------------------------------
// Fused aggregation: out[d] = act( dinv[d]^2*H[d] + sum_e w[e]*H[src[e]] + b )
// One warp per node. No atomics.
// ---------------------------------------------------------------------------
template <int F, int ACT>
__global__ void agg_fused(const float* __restrict__ H,
                          const int* __restrict__ rowstart,
                          const int* __restrict__ deg,
                          const int* __restrict__ csr_src,
                          const float* __restrict__ csr_w,
                          const float* __restrict__ dinv,
                          const float* __restrict__ bias,
                          float* __restrict__ out, int M) {
    constexpr int V = F / 32;          // floats per lane (4 or 2)
    int warp = (blockIdx.x * blockDim.x + threadIdx.x) >> 5;
    if (warp >= M) return;
    int lane = threadIdx.x & 31;

    float acc[V];
    {
        float dv = dinv[warp];
        float s = dv * dv;
        if (V == 4) {
            float4 v = *(const float4*)(H + (size_t)warp * F + lane * 4);
            acc[0] = s * v.x; acc[1] = s * v.y; acc[2] = s * v.z; acc[3] = s * v.w;
        } else {
            float2 v = *(const float2*)(H + (size_t)warp * F + lane * 2);
            acc[0] = s * v.x; acc[1] = s * v.y;
        }
    }

    int beg = rowstart[warp];
    int n = deg[warp];
    int j = 0;
    for (; j + 2 <= n; j += 2) {
        int s0 = csr_src[beg + j];
        int s1 = csr_src[beg + j + 1];
        float w0 = csr_w[beg + j];
        float w1 = csr_w[beg + j + 1];
        if (V == 4) {
            float4 v0 = *(const float4*)(H + (size_t)s0 * F + lane * 4);
            float4 v1 = *(const float4*)(H + (size_t)s1 * F + lane * 4);
            acc[0] = fmaf(w0, v0.x, acc[0]); acc[1] = fmaf(w0, v0.y, acc[1]);
            acc[2] = fmaf(w0, v0.z, acc[2]); acc[3] = fmaf(w0, v0.w, acc[3]);
            acc[0] = fmaf(w1, v1.x, acc[0]); acc[1] = fmaf(w1, v1.y, acc[1]);
            acc[2] = fmaf(w1, v1.z, acc[2]); acc[3] = fmaf(w1, v1.w, acc[3]);
        } else {
            float2 v0 = *(const float2*)(H + (size_t)s0 * F + lane * 2);
            float2 v1 = *(const float2*)(H + (size_t)s1 * F + lane * 2);
            acc[0] = fmaf(w0, v0.x, acc[0]); acc[1] = fmaf(w0, v0.y, acc[1]);
            acc[0] = fmaf(w1, v1.x, acc[0]); acc[1] = fmaf(w1, v1.y, acc[1]);
        }
    }
    if (j < n) {
        int s0 = csr_src[beg + j];
        float w0 = csr_w[beg + j];
        if (V == 4) {
            float4 v0 = *(const float4*)(H + (size_t)s0 * F + lane * 4);
            acc[0] = fmaf(w0, v0.x, acc[0]); acc[1] = fmaf(w0, v0.y, acc[1]);
            acc[2] = fmaf(w0, v0.z, acc[2]); acc[3] = fmaf(w0, v0.w, acc[3]);
        } else {
            float2 v0 = *(const float2*)(H + (size_t)s0 * F + lane * 2);
            acc[0] = fmaf(w0, v0.x, acc[0]); acc[1] = fmaf(w0, v0.y, acc[1]);
        }
    }

    if (V == 4) {
        float4 b = *(const float4*)(bias + lane * 4);
        acc[0] += b.x; acc[1] += b.y; acc[2] += b.z; acc[3] += b.w;
        if (ACT) {
            acc[0] = tanhf(acc[0]); acc[1] = tanhf(acc[1]);
            acc[2] = tanhf(acc[2]); acc[3] = tanhf(acc[3]);
        }
        *(float4*)(out + (size_t)warp * F + lane * 4) =
            make_float4(acc[0], acc[1], acc[2], acc[3]);
    } else {
        float2 b = *(const float2*)(bias + lane * 2);
        acc[0] += b.x; acc[1] += b.y;
        if (ACT) { acc[0] = tanhf(acc[0]); acc[1] = tanhf(acc[1]); }
        *(float2*)(out + (size_t)warp * F + lane * 2) = make_float2(acc[0], acc[1]);
    }
}

// ---------------------------------------------------------------------------
// Host side
// ---------------------------------------------------------------------------
extern "C" void kernel_launch(void* const* d_in, const int* in_sizes, int n_in,
                              void* d_out, int out_size) {
    const float* feat = (const float*)d_in[0];   // [N,128] f32
    const float* cond = (const float*)d_in[1];   // [N,32]  f32
    const int*   ei   = (const int*)d_in[2];     // [2,E] int32
    const float* We1 = (const float*)d_in[3];
    const float* be1 = (const float*)d_in[4];
    const float* We2 = (const float*)d_in[5];
    const float* be2 = (const float*)d_in[6];
    const float* We3 = (const float*)d_in[7];
    const float* be3 = (const float*)d_in[8];
    const float* Wd1 = (const float*)d_in[9];
    const float* bd1 = (const float*)d_in[10];
    const float* Wd2 = (const float*)d_in[11];
    const float* bd2 = (const float*)d_in[12];
    const float* Wd3 = (const float*)d_in[13];
    const float* bd3 = (const float*)d_in[14];

    const int N = in_sizes[0] / 128;
    const int E = in_sizes[2] / 2;
    const int* src = ei;
    const int* dst = ei + E;
    float* out = (float*)d_out;

    float *dinv, *buf1, *buf2, *csr_w;
    int *deg, *rowstart, *cursor, *csr_src, *gcur;
    cudaGetSymbolAddress((void**)&dinv, g_dinv);
    cudaGetSymbolAddress((void**)&deg, g_deg);
    cudaGetSymbolAddress((void**)&rowstart, g_rowstart);
    cudaGetSymbolAddress((void**)&cursor, g_cursor);
    cudaGetSymbolAddress((void**)&csr_src, g_csr_src);
    cudaGetSymbolAddress((void**)&csr_w, g_csr_w);
    cudaGetSymbolAddress((void**)&buf1, g_buf1);
    cudaGetSymbolAddress((void**)&buf2, g_buf2);
    cudaGetSymbolAddress((void**)&gcur, g_gcur);

    // ---- CSR build (once per launch) ----
    reset_counters<<<cdiv(N, 256), 256>>>(deg, gcur, N);
    deg_count<<<cdiv(E, 256), 256>>>(dst, deg, E);
    dinv_compute<<<cdiv(N, 256), 256>>>(deg, dinv, N);
    assign_rows<<<cdiv(N, 256), 256>>>(deg, rowstart, cursor, gcur, N);
    csr_fill<<<cdiv(E, 256), 256>>>(src, dst, dinv, cursor, csr_src, csr_w, E);

    dim3 g128(1, cdiv(N, 128));
    const int aggBlocks128 = cdiv(N * 32, 256);

    // encoder layer 1: [feat|cond] (K=160) -> 128, tanh
    gemm_concat<128, 128, 16, 8, 8><<<g128, 256>>>(feat, 128, cond, 32, We1, buf1, N, 128);
    agg_fused<128, 1><<<aggBlocks128, 256>>>(buf1, rowstart, deg, csr_src, csr_w, dinv, be1, buf2, N);

    // encoder layer 2: 128 -> 128, tanh
    gemm_concat<128, 128, 16, 8, 8><<<g128, 256>>>(buf2, 128, nullptr, 0, We2, buf1, N, 128);
    agg_fused<128, 1><<<aggBlocks128, 256>>>(buf1, rowstart, deg, csr_src, csr_w, dinv, be2, buf2, N);

    // encoder layer 3: 128 -> 64 (z), no activation
    gemm_concat<128, 64, 16, 8, 4><<<g128, 256>>>(buf2, 128, nullptr, 0, We3, buf1, N, 64);
    agg_fused<64, 0><<<aggBlocks128, 256>>>(buf1, rowstart, deg, csr_src, csr_w, dinv, be3, buf2, N);

    // decoder layer 1: [z|cond] (K=96) -> 128, tanh
    gemm_concat<128, 128, 16, 8, 8><<<g128, 256>>>(buf2, 64, cond, 32, Wd1, buf1, N, 128);
    agg_fused<128, 1><<<aggBlocks128, 256>>>(buf1, rowstart, deg, csr_src, csr_w, dinv, bd1, buf2, N);

    // decoder layer 2: 128 -> 128, tanh
    gemm_concat<128, 128, 16, 8, 8><<<g128, 256>>>(buf2, 128, nullptr, 0, Wd2, buf1, N, 128);
    agg_fused<128, 1><<<aggBlocks128, 256>>>(buf1, rowstart, deg, csr_src, csr_w, dinv, bd2, buf2, N);

    // decoder layer 3: 128 -> 128, no activation, write to d_out
    gemm_concat<128, 128, 16, 8, 8><<<g128, 256>>>(buf2, 128, nullptr, 0, Wd3, buf1, N, 128);
    agg_fused<128, 0><<<aggBlocks128, 256>>>(buf1, rowstart, deg, csr_src, csr_w, dinv, bd3, out, N);
}

// round 7
// speedup vs baseline: 2.3409x; 1.3090x over previous
#include <cuda_runtime.h>
#include <cuda_bf16.h>
#include <stdint.h>
#include <math.h>

// Problem constants (fixed by the dataset)
#define NN 100000
#define EE 1600000

// Scratch (allocation-free rule: static __device__ globals).
__device__ __align__(256) float g_dinv[NN];
__device__ __align__(256) int   g_deg[NN];
__device__ __align__(256) int   g_rowstart[NN];
__device__ __align__(256) int   g_cursor[NN];
__device__ __align__(256) int   g_csr_src[EE];
__device__ __align__(256) float g_csr_w[EE];
__device__ __align__(256) float g_buf1[NN * 128];
__device__ __align__(256) float g_buf2[NN * 128];
__device__ int g_gcur;

static inline int cdiv(int a, int b) { return (a + b - 1) / b; }

// ---------------------------------------------------------------------------
// CSR construction (edge_index is int32)
// ---------------------------------------------------------------------------
__global__ void reset_counters(int* deg, int* gcur, int n) {
    int i = blockIdx.x * blockDim.x + threadIdx.x;
    if (i < n) deg[i] = 0;
    if (i == 0) *gcur = 0;
}

__global__ void deg_count(const int* __restrict__ dst, int* __restrict__ deg, int E) {
    int i = blockIdx.x * blockDim.x + threadIdx.x;
    if (i < E) atomicAdd(&deg[dst[i]], 1);
}

__global__ void dinv_compute(const int* __restrict__ deg, float* __restrict__ dinv, int n) {
    int i = blockIdx.x * blockDim.x + threadIdx.x;
    if (i < n) dinv[i] = rsqrtf((float)deg[i] + 1.0f);
}

__global__ void assign_rows(const int* __restrict__ deg, int* __restrict__ rowstart,
                            int* __restrict__ cursor, int* gcur, int n) {
    int i = blockIdx.x * blockDim.x + threadIdx.x;
    int lane = threadIdx.x & 31;
    int d = (i < n) ? deg[i] : 0;
    int incl = d;
#pragma unroll
    for (int o = 1; o < 32; o <<= 1) {
        int v = __shfl_up_sync(0xFFFFFFFFu, incl, o);
        if (lane >= o) incl += v;
    }
    int total = __shfl_sync(0xFFFFFFFFu, incl, 31);
    int base = 0;
    if (lane == 31) base = atomicAdd(gcur, total);
    base = __shfl_sync(0xFFFFFFFFu, base, 31);
    int excl = incl - d;
    if (i < n) {
        rowstart[i] = base + excl;
        cursor[i]   = base + excl;
    }
}

__global__ void csr_fill(const int* __restrict__ src, const int* __restrict__ dst,
                         const float* __restrict__ dinv,
                         int* __restrict__ cursor,
                         int* __restrict__ csr_src, float* __restrict__ csr_w, int E) {
    int i = blockIdx.x * blockDim.x + threadIdx.x;
    if (i >= E) return;
    int s = src[i];
    int d = dst[i];
    int pos = atomicAdd(&cursor[d], 1);
    csr_src[pos] = s;
    csr_w[pos] = dinv[s] * dinv[d];
}

// ---------------------------------------------------------------------------
// bf16-split tensor-core GEMM
// out[M, Nout] = concat(xA[:,0:KA], xB[:,0:KB]) @ W[K, Nout]
// fp32 operands split as x = hi + lo (both bf16); fp32 accum via
// mma.sync.m16n8k16: A_hi*B_hi + A_hi*B_lo + A_lo*B_hi.
// Fixed: BM=128, BK=32, 256 threads (8 warps, 4x2 warp grid).
// ---------------------------------------------------------------------------
__device__ __forceinline__ void ldsm_x4(uint32_t a, uint32_t& r0, uint32_t& r1,
                                        uint32_t& r2, uint32_t& r3) {
    asm volatile("ldmatrix.sync.aligned.m8n8.x4.shared.b16 {%0,%1,%2,%3}, [%4];"
                 : "=r"(r0), "=r"(r1), "=r"(r2), "=r"(r3) : "r"(a));
}
__device__ __forceinline__ void ldsm_x4_t(uint32_t a, uint32_t& r0, uint32_t& r1,
                                          uint32_t& r2, uint32_t& r3) {
    asm volatile("ldmatrix.sync.aligned.m8n8.x4.trans.shared.b16 {%0,%1,%2,%3}, [%4];"
                 : "=r"(r0), "=r"(r1), "=r"(r2), "=r"(r3) : "r"(a));
}
__device__ __forceinline__ void mma_bf16(float* c, const uint32_t* a, const uint32_t* b) {
    asm volatile(
        "mma.sync.aligned.m16n8k16.row.col.f32.bf16.bf16.f32 "
        "{%0,%1,%2,%3}, {%4,%5,%6,%7}, {%8,%9}, {%0,%1,%2,%3};"
        : "+f"(c[0]), "+f"(c[1]), "+f"(c[2]), "+f"(c[3])
        : "r"(a[0]), "r"(a[1]), "r"(a[2]), "r"(a[3]), "r"(b[0]), "r"(b[1]));
}
__device__ __forceinline__ void split_bf16(float x, __nv_bfloat16& h, __nv_bfloat16& l) {
    h = __float2bfloat16_rn(x);
    l = __float2bfloat16_rn(x - __bfloat162float(h));
}

template <int BN>
__global__ __launch_bounds__(256)
void gemm_mma(const float* __restrict__ xA, int KA,
              const float* __restrict__ xB, int KB,
              const float* __restrict__ W,
              float* __restrict__ out, int M, int Nout) {
    constexpr int BM = 128, BK = 32;
    constexpr int XS = BK + 8;                 // X smem row stride (bf16 elems) = 80 B
    constexpr int WS = BN + 8;                 // W smem row stride
    constexpr int WN = BN / 2;                 // warp n-extent (2 warps in n)
    constexpr int NT = WN / 8;                 // n8 tiles per warp
    constexpr int MT = 2;                      // m16 tiles per warp (WM=32)

    __shared__ __nv_bfloat16 Xhi[BM * XS], Xlo[BM * XS];
    __shared__ __nv_bfloat16 Whi[BK * WS], Wlo[BK * WS];

    const int K = KA + KB;
    const int tid = threadIdx.x;
    const int warp = tid >> 5;
    const int lane = tid & 31;
    const int warp_m = warp >> 1;              // 0..3
    const int warp_n = warp & 1;               // 0..1
    const int rowBase = blockIdx.y * BM;

    float acc[MT][NT][4];
#pragma unroll
    for (int i = 0; i < MT; i++)
#pragma unroll
        for (int j = 0; j < NT; j++)
#pragma unroll
            for (int q = 0; q < 4; q++) acc[i][j][q] = 0.0f;

    const uint32_t xhi_b = (uint32_t)__cvta_generic_to_shared(Xhi);
    const uint32_t xlo_b = (uint32_t)__cvta_generic_to_shared(Xlo);
    const uint32_t whi_b = (uint32_t)__cvta_generic_to_shared(Whi);
    const uint32_t wlo_b = (uint32_t)__cvta_generic_to_shared(Wlo);

    for (int k0 = 0; k0 < K; k0 += BK) {
        // ---- load & split X tile: BM x BK ----
        for (int idx = tid; idx < BM * (BK / 4); idx += 256) {
            int r = idx / (BK / 4);
            int kq = idx % (BK / 4);
            int gr = rowBase + r;
            int k = k0 + kq * 4;
            float4 v = make_float4(0.f, 0.f, 0.f, 0.f);
            if (gr < M) {
                const float* p = (k < KA)
                    ? (xA + (size_t)gr * KA + k)
                    : (xB + (size_t)gr * KB + (k - KA));
                v = *(const float4*)p;
            }
            __nv_bfloat16 h0, h1, h2, h3, l0, l1, l2, l3;
            split_bf16(v.x, h0, l0); split_bf16(v.y, h1, l1);
            split_bf16(v.z, h2, l2); split_bf16(v.w, h3, l3);
            int o = r * XS + kq * 4;
            *(__nv_bfloat162*)&Xhi[o]     = __nv_bfloat162(h0, h1);
            *(__nv_bfloat162*)&Xhi[o + 2] = __nv_bfloat162(h2, h3);
            *(__nv_bfloat162*)&Xlo[o]     = __nv_bfloat162(l0, l1);
            *(__nv_bfloat162*)&Xlo[o + 2] = __nv_bfloat162(l2, l3);
        }
        // ---- load & split W tile: BK x BN ----
        for (int idx = tid; idx < BK * (BN / 4); idx += 256) {
            int kr = idx / (BN / 4);
            int nc = idx % (BN / 4);
            float4 v = *(const float4*)(W + (size_t)(k0 + kr) * Nout + nc * 4);
            __nv_bfloat16 h0, h1, h2, h3, l0, l1, l2, l3;
            split_bf16(v.x, h0, l0); split_bf16(v.y, h1, l1);
            split_bf16(v.z, h2, l2); split_bf16(v.w, h3, l3);
            int o = kr * WS + nc * 4;
            *(__nv_bfloat162*)&Whi[o]     = __nv_bfloat162(h0, h1);
            *(__nv_bfloat162*)&Whi[o + 2] = __nv_bfloat162(h2, h3);
            *(__nv_bfloat162*)&Wlo[o]     = __nv_bfloat162(l0, l1);
            *(__nv_bfloat162*)&Wlo[o + 2] = __nv_bfloat162(l2, l3);
        }
        __syncthreads();

#pragma unroll
        for (int ks = 0; ks < BK / 16; ks++) {
            // A fragments (hi, lo) for MT m-tiles
            uint32_t ahi[MT][4];
            uint32_t alo[MT][4];
#pragma unroll
            for (int mt = 0; mt < MT; mt++) {
                int r = warp_m * 32 + mt * 16 + (lane & 15);
                int c = ks * 16 + (lane >> 4) * 8;
                uint32_t off = (uint32_t)(r * XS + c) * 2;
                ldsm_x4(xhi_b + off, ahi[mt][0], ahi[mt][1], ahi[mt][2], ahi[mt][3]);
                ldsm_x4(xlo_b + off, alo[mt][0], alo[mt][1], alo[mt][2], alo[mt][3]);
            }
            // B fragments (hi, lo) for NT n-tiles (loaded in 16-col pairs)
            uint32_t bhi[NT][2];
            uint32_t blo[NT][2];
#pragma unroll
            for (int np = 0; np < NT / 2; np++) {
                int r = ks * 16 + (lane & 15);
                int c = warp_n * WN + np * 16 + (lane >> 4) * 8;
                uint32_t off = (uint32_t)(r * WS + c) * 2;
                ldsm_x4_t(whi_b + off, bhi[2 * np][0], bhi[2 * np][1],
                          bhi[2 * np + 1][0], bhi[2 * np + 1][1]);
                ldsm_x4_t(wlo_b + off, blo[2 * np][0], blo[2 * np][1],
                          blo[2 * np + 1][0], blo[2 * np + 1][1]);
            }
#pragma unroll
            for (int mt = 0; mt < MT; mt++)
#pragma unroll
                for (int nt = 0; nt < NT; nt++) {
                    mma_bf16(acc[mt][nt], ahi[mt], bhi[nt]);
                    mma_bf16(acc[mt][nt], ahi[mt], blo[nt]);
                    mma_bf16(acc[mt][nt], alo[mt], bhi[nt]);
                }
        }
        __syncthreads();
    }

    // ---- store ----
#pragma unroll
    for (int mt = 0; mt < MT; mt++) {
#pragma unroll
        for (int nt = 0; nt < NT; nt++) {
            int row = rowBase + warp_m * 32 + mt * 16 + (lane >> 2);
            int col = warp_n * WN + nt * 8 + (lane & 3) * 2;
            if (row < M)
                *(float2*)(out + (size_t)row * Nout + col) =
                    make_float2(acc[mt][nt][0], acc[mt][nt][1]);
            if (row + 8 < M)
                *(float2*)(out + (size_t)(row + 8) * Nout + col) =
                    make_float2(acc[mt][nt][2], acc[mt][nt][3]);
        }
    }
}

// ---------------------------------------------------------------------------
// Fused aggregation: out[d] = act( dinv[d]^2*H[d] + sum_e w[e]*H[src[e]] + b )
// One warp per node. No atomics.
// ---------------------------------------------------------------------------
template <int F, int ACT>
__global__ void agg_fused(const float* __restrict__ H,
                          const int* __restrict__ rowstart,
                          const int* __restrict__ deg,
                          const int* __restrict__ csr_src,
                          const float* __restrict__ csr_w,
                          const float* __restrict__ dinv,
                          const float* __restrict__ bias,
                          float* __restrict__ out, int M) {
    constexpr int V = F / 32;
    int warp = (blockIdx.x * blockDim.x + threadIdx.x) >> 5;
    if (warp >= M) return;
    int lane = threadIdx.x & 31;

    float acc[V];
    {
        float dv = dinv[warp];
        float s = dv * dv;
        if (V == 4) {
            float4 v = *(const float4*)(H + (size_t)warp * F + lane * 4);
            acc[0] = s * v.x; acc[1] = s * v.y; acc[2] = s * v.z; acc[3] = s * v.w;
        } else {
            float2 v = *(const float2*)(H + (size_t)warp * F + lane * 2);
            acc[0] = s * v.x; acc[1] = s * v.y;
        }
    }

    int beg = rowstart[warp];
    int n = deg[warp];
    int j = 0;
    for (; j + 2 <= n; j += 2) {
        int s0 = csr_src[beg + j];
        int s1 = csr_src[beg + j + 1];
        float w0 = csr_w[beg + j];
        float w1 = csr_w[beg + j + 1];
        if (V == 4) {
            float4 v0 = *(const float4*)(H + (size_t)s0 * F + lane * 4);
            float4 v1 = *(const float4*)(H + (size_t)s1 * F + lane * 4);
            acc[0] = fmaf(w0, v0.x, acc[0]); acc[1] = fmaf(w0, v0.y, acc[1]);
            acc[2] = fmaf(w0, v0.z, acc[2]); acc[3] = fmaf(w0, v0.w, acc[3]);
            acc[0] = fmaf(w1, v1.x, acc[0]); acc[1] = fmaf(w1, v1.y, acc[1]);
            acc[2] = fmaf(w1, v1.z, acc[2]); acc[3] = fmaf(w1, v1.w, acc[3]);
        } else {
            float2 v0 = *(const float2*)(H + (size_t)s0 * F + lane * 2);
            float2 v1 = *(const float2*)(H + (size_t)s1 * F + lane * 2);
            acc[0] = fmaf(w0, v0.x, acc[0]); acc[1] = fmaf(w0, v0.y, acc[1]);
            acc[0] = fmaf(w1, v1.x, acc[0]); acc[1] = fmaf(w1, v1.y, acc[1]);
        }
    }
    if (j < n) {
        int s0 = csr_src[beg + j];
        float w0 = csr_w[beg + j];
        if (V == 4) {
            float4 v0 = *(const float4*)(H + (size_t)s0 * F + lane * 4);
            acc[0] = fmaf(w0, v0.x, acc[0]); acc[1] = fmaf(w0, v0.y, acc[1]);
            acc[2] = fmaf(w0, v0.z, acc[2]); acc[3] = fmaf(w0, v0.w, acc[3]);
        } else {
            float2 v0 = *(const float2*)(H + (size_t)s0 * F + lane * 2);
            acc[0] = fmaf(w0, v0.x, acc[0]); acc[1] = fmaf(w0, v0.y, acc[1]);
        }
    }

    if (V == 4) {
        float4 b = *(const float4*)(bias + lane * 4);
        acc[0] += b.x; acc[1] += b.y; acc[2] += b.z; acc[3] += b.w;
        if (ACT) {
            acc[0] = tanhf(acc[0]); acc[1] = tanhf(acc[1]);
            acc[2] = tanhf(acc[2]); acc[3] = tanhf(acc[3]);
        }
        *(float4*)(out + (size_t)warp * F + lane * 4) =
            make_float4(acc[0], acc[1], acc[2], acc[3]);
    } else {
        float2 b = *(const float2*)(bias + lane * 2);
        acc[0] += b.x; acc[1] += b.y;
        if (ACT) { acc[0] = tanhf(acc[0]); acc[1] = tanhf(acc[1]); }
        *(float2*)(out + (size_t)warp * F + lane * 2) = make_float2(acc[0], acc[1]);
    }
}

// ---------------------------------------------------------------------------
// Host side
// ---------------------------------------------------------------------------
extern "C" void kernel_launch(void* const* d_in, const int* in_sizes, int n_in,
                              void* d_out, int out_size) {
    const float* feat = (const float*)d_in[0];   // [N,128] f32
    const float* cond = (const float*)d_in[1];   // [N,32]  f32
    const int*   ei   = (const int*)d_in[2];     // [2,E] int32
    const float* We1 = (const float*)d_in[3];
    const float* be1 = (const float*)d_in[4];
    const float* We2 = (const float*)d_in[5];
    const float* be2 = (const float*)d_in[6];
    const float* We3 = (const float*)d_in[7];
    const float* be3 = (const float*)d_in[8];
    const float* Wd1 = (const float*)d_in[9];
    const float* bd1 = (const float*)d_in[10];
    const float* Wd2 = (const float*)d_in[11];
    const float* bd2 = (const float*)d_in[12];
    const float* Wd3 = (const float*)d_in[13];
    const float* bd3 = (const float*)d_in[14];

    const int N = in_sizes[0] / 128;
    const int E = in_sizes[2] / 2;
    const int* src = ei;
    const int* dst = ei + E;
    float* out = (float*)d_out;

    float *dinv, *buf1, *buf2, *csr_w;
    int *deg, *rowstart, *cursor, *csr_src, *gcur;
    cudaGetSymbolAddress((void**)&dinv, g_dinv);
    cudaGetSymbolAddress((void**)&deg, g_deg);
    cudaGetSymbolAddress((void**)&rowstart, g_rowstart);
    cudaGetSymbolAddress((void**)&cursor, g_cursor);
    cudaGetSymbolAddress((void**)&csr_src, g_csr_src);
    cudaGetSymbolAddress((void**)&csr_w, g_csr_w);
    cudaGetSymbolAddress((void**)&buf1, g_buf1);
    cudaGetSymbolAddress((void**)&buf2, g_buf2);
    cudaGetSymbolAddress((void**)&gcur, g_gcur);

    // ---- CSR build (once per launch) ----
    reset_counters<<<cdiv(N, 256), 256>>>(deg, gcur, N);
    deg_count<<<cdiv(E, 256), 256>>>(dst, deg, E);
    dinv_compute<<<cdiv(N, 256), 256>>>(deg, dinv, N);
    assign_rows<<<cdiv(N, 256), 256>>>(deg, rowstart, cursor, gcur, N);
    csr_fill<<<cdiv(E, 256), 256>>>(src, dst, dinv, cursor, csr_src, csr_w, E);

    dim3 gB(1, cdiv(N, 128));
    const int aggBlocks = cdiv(N * 32, 256);

    // encoder layer 1: [feat|cond] (K=160) -> 128, tanh
    gemm_mma<128><<<gB, 256>>>(feat, 128, cond, 32, We1, buf1, N, 128);
    agg_fused<128, 1><<<aggBlocks, 256>>>(buf1, rowstart, deg, csr_src, csr_w, dinv, be1, buf2, N);

    // encoder layer 2: 128 -> 128, tanh
    gemm_mma<128><<<gB, 256>>>(buf2, 128, nullptr, 0, We2, buf1, N, 128);
    agg_fused<128, 1><<<aggBlocks, 256>>>(buf1, rowstart, deg, csr_src, csr_w, dinv, be2, buf2, N);

    // encoder layer 3: 128 -> 64 (z), no activation
    gemm_mma<64><<<gB, 256>>>(buf2, 128, nullptr, 0, We3, buf1, N, 64);
    agg_fused<64, 0><<<aggBlocks, 256>>>(buf1, rowstart, deg, csr_src, csr_w, dinv, be3, buf2, N);

    // decoder layer 1: [z|cond] (K=96) -> 128, tanh
    gemm_mma<128><<<gB, 256>>>(buf2, 64, cond, 32, Wd1, buf1, N, 128);
    agg_fused<128, 1><<<aggBlocks, 256>>>(buf1, rowstart, deg, csr_src, csr_w, dinv, bd1, buf2, N);

    // decoder layer 2: 128 -> 128, tanh
    gemm_mma<128><<<gB, 256>>>(buf2, 128, nullptr, 0, Wd2, buf1, N, 128);
    agg_fused<128, 1><<<aggBlocks, 256>>>(buf1, rowstart, deg, csr_src, csr_w, dinv, bd2, buf2, N);

    // decoder layer 3: 128 -> 128, no activation, write to d_out
    gemm_mma<128><<<gB, 256>>>(buf2, 128, nullptr, 0, Wd3, buf1, N, 128);
    agg_fused<128, 0><<<aggBlocks, 256>>>(buf1, rowstart, deg, csr_src, csr_w, dinv, bd3, out, N);
}

// round 9
// speedup vs baseline: 2.3513x; 1.0044x over previous
#include <cuda_runtime.h>
#include <cuda_bf16.h>
#include <cuda_fp16.h>
#include <stdint.h>
#include <math.h>

// Problem constants (fixed by the dataset)
#define NN 100000
#define EE 1600000

// Scratch (allocation-free rule: static __device__ globals).
__device__ __align__(256) float  g_dinv[NN];
__device__ __align__(256) int    g_deg[NN];
__device__ __align__(256) int    g_rowstart[NN];
__device__ __align__(256) int    g_cursor[NN];
__device__ __align__(256) int    g_csr_src[EE];
__device__ __align__(256) float  g_csr_w[EE];
__device__ __align__(256) float  g_buf1[NN * 128];   // GEMM out (fp32, for self term)
__device__ __align__(256) float  g_buf2[NN * 128];   // agg out / next GEMM in
__device__ __align__(256) __half g_h16[NN * 128];    // GEMM out (fp16, for gathers)
__device__ int g_gcur;

static inline int cdiv(int a, int b) { return (a + b - 1) / b; }

// ---------------------------------------------------------------------------
// CSR construction (edge_index is int32)
// ---------------------------------------------------------------------------
__global__ void reset_counters(int* deg, int* gcur, int n) {
    int i = blockIdx.x * blockDim.x + threadIdx.x;
    if (i < n) deg[i] = 0;
    if (i == 0) *gcur = 0;
}

__global__ void deg_count(const int* __restrict__ dst, int* __restrict__ deg, int E) {
    int i = blockIdx.x * blockDim.x + threadIdx.x;
    if (i < E) atomicAdd(&deg[dst[i]], 1);
}

__global__ void dinv_compute(const int* __restrict__ deg, float* __restrict__ dinv, int n) {
    int i = blockIdx.x * blockDim.x + threadIdx.x;
    if (i < n) dinv[i] = rsqrtf((float)deg[i] + 1.0f);
}

__global__ void assign_rows(const int* __restrict__ deg, int* __restrict__ rowstart,
                            int* __restrict__ cursor, int* gcur, int n) {
    int i = blockIdx.x * blockDim.x + threadIdx.x;
    int lane = threadIdx.x & 31;
    int d = (i < n) ? deg[i] : 0;
    int incl = d;
#pragma unroll
    for (int o = 1; o < 32; o <<= 1) {
        int v = __shfl_up_sync(0xFFFFFFFFu, incl, o);
        if (lane >= o) incl += v;
    }
    int total = __shfl_sync(0xFFFFFFFFu, incl, 31);
    int base = 0;
    if (lane == 31) base = atomicAdd(gcur, total);
    base = __shfl_sync(0xFFFFFFFFu, base, 31);
    int excl = incl - d;
    if (i < n) {
        rowstart[i] = base + excl;
        cursor[i]   = base + excl;
    }
}

__global__ void csr_fill(const int* __restrict__ src, const int* __restrict__ dst,
                         const float* __restrict__ dinv,
                         int* __restrict__ cursor,
                         int* __restrict__ csr_src, float* __restrict__ csr_w, int E) {
    int i = blockIdx.x * blockDim.x + threadIdx.x;
    if (i >= E) return;
    int s = src[i];
    int d = dst[i];
    int pos = atomicAdd(&cursor[d], 1);
    csr_src[pos] = s;
    csr_w[pos] = dinv[s] * dinv[d];
}

// ---------------------------------------------------------------------------
// bf16-split tensor-core GEMM (+ fp16 shadow output for aggregation gathers)
// out[M, Nout] = concat(xA[:,0:KA], xB[:,0:KB]) @ W[K, Nout]
// ---------------------------------------------------------------------------
__device__ __forceinline__ void ldsm_x4(uint32_t a, uint32_t& r0, uint32_t& r1,
                                        uint32_t& r2, uint32_t& r3) {
    asm volatile("ldmatrix.sync.aligned.m8n8.x4.shared.b16 {%0,%1,%2,%3}, [%4];"
                 : "=r"(r0), "=r"(r1), "=r"(r2), "=r"(r3) : "r"(a));
}
__device__ __forceinline__ void ldsm_x4_t(uint32_t a, uint32_t& r0, uint32_t& r1,
                                          uint32_t& r2, uint32_t& r3) {
    asm volatile("ldmatrix.sync.aligned.m8n8.x4.trans.shared.b16 {%0,%1,%2,%3}, [%4];"
                 : "=r"(r0), "=r"(r1), "=r"(r2), "=r"(r3) : "r"(a));
}
__device__ __forceinline__ void mma_bf16(float* c, const uint32_t* a, const uint32_t* b) {
    asm volatile(
        "mma.sync.aligned.m16n8k16.row.col.f32.bf16.bf16.f32 "
        "{%0,%1,%2,%3}, {%4,%5,%6,%7}, {%8,%9}, {%0,%1,%2,%3};"
        : "+f"(c[0]), "+f"(c[1]), "+f"(c[2]), "+f"(c[3])
        : "r"(a[0]), "r"(a[1]), "r"(a[2]), "r"(a[3]), "r"(b[0]), "r"(b[1]));
}
__device__ __forceinline__ void split_bf16(float x, __nv_bfloat16& h, __nv_bfloat16& l) {
    h = __float2bfloat16_rn(x);
    l = __float2bfloat16_rn(x - __bfloat162float(h));
}

template <int BN>
__global__ __launch_bounds__(256)
void gemm_mma(const float* __restrict__ xA, int KA,
              const float* __restrict__ xB, int KB,
              const float* __restrict__ W,
              float* __restrict__ out, __half* __restrict__ out16,
              int M, int Nout) {
    constexpr int BM = 128, BK = 32;
    constexpr int XS = BK + 8;
    constexpr int WS = BN + 8;
    constexpr int WN = BN / 2;
    constexpr int NT = WN / 8;
    constexpr int MT = 2;

    __shared__ __nv_bfloat16 Xhi[BM * XS], Xlo[BM * XS];
    __shared__ __nv_bfloat16 Whi[BK * WS], Wlo[BK * WS];

    const int K = KA + KB;
    const int tid = threadIdx.x;
    const int warp = tid >> 5;
    const int lane = tid & 31;
    const int warp_m = warp >> 1;
    const int warp_n = warp & 1;
    const int rowBase = blockIdx.y * BM;

    float acc[MT][NT][4];
#pragma unroll
    for (int i = 0; i < MT; i++)
#pragma unroll
        for (int j = 0; j < NT; j++)
#pragma unroll
            for (int q = 0; q < 4; q++) acc[i][j][q] = 0.0f;

    const uint32_t xhi_b = (uint32_t)__cvta_generic_to_shared(Xhi);
    const uint32_t xlo_b = (uint32_t)__cvta_generic_to_shared(Xlo);
    const uint32_t whi_b = (uint32_t)__cvta_generic_to_shared(Whi);
    const uint32_t wlo_b = (uint32_t)__cvta_generic_to_shared(Wlo);

    for (int k0 = 0; k0 < K; k0 += BK) {
        for (int idx = tid; idx < BM * (BK / 4); idx += 256) {
            int r = idx / (BK / 4);
            int kq = idx % (BK / 4);
            int gr = rowBase + r;
            int k = k0 + kq * 4;
            float4 v = make_float4(0.f, 0.f, 0.f, 0.f);
            if (gr < M) {
                const float* p = (k < KA)
                    ? (xA + (size_t)gr * KA + k)
                    : (xB + (size_t)gr * KB + (k - KA));
                v = *(const float4*)p;
            }
            __nv_bfloat16 h0, h1, h2, h3, l0, l1, l2, l3;
            split_bf16(v.x, h0, l0); split_bf16(v.y, h1, l1);
            split_bf16(v.z, h2, l2); split_bf16(v.w, h3, l3);
            int o = r * XS + kq * 4;
            *(__nv_bfloat162*)&Xhi[o]     = __nv_bfloat162(h0, h1);
            *(__nv_bfloat162*)&Xhi[o + 2] = __nv_bfloat162(h2, h3);
            *(__nv_bfloat162*)&Xlo[o]     = __nv_bfloat162(l0, l1);
            *(__nv_bfloat162*)&Xlo[o + 2] = __nv_bfloat162(l2, l3);
        }
        for (int idx = tid; idx < BK * (BN / 4); idx += 256) {
            int kr = idx / (BN / 4);
            int nc = idx % (BN / 4);
            float4 v = *(const float4*)(W + (size_t)(k0 + kr) * Nout + nc * 4);
            __nv_bfloat16 h0, h1, h2, h3, l0, l1, l2, l3;
            split_bf16(v.x, h0, l0); split_bf16(v.y, h1, l1);
            split_bf16(v.z, h2, l2); split_bf16(v.w, h3, l3);
            int o = kr * WS + nc * 4;
            *(__nv_bfloat162*)&Whi[o]     = __nv_bfloat162(h0, h1);
            *(__nv_bfloat162*)&Whi[o + 2] = __nv_bfloat162(h2, h3);
            *(__nv_bfloat162*)&Wlo[o]     = __nv_bfloat162(l0, l1);
            *(__nv_bfloat162*)&Wlo[o + 2] = __nv_bfloat162(l2, l3);
        }
        __syncthreads();

#pragma unroll
        for (int ks = 0; ks < BK / 16; ks++) {
            uint32_t ahi[MT][4];
            uint32_t alo[MT][4];
#pragma unroll
            for (int mt = 0; mt < MT; mt++) {
                int r = warp_m * 32 + mt * 16 + (lane & 15);
                int c = ks * 16 + (lane >> 4) * 8;
                uint32_t off = (uint32_t)(r * XS + c) * 2;
                ldsm_x4(xhi_b + off, ahi[mt][0], ahi[mt][1], ahi[mt][2], ahi[mt][3]);
                ldsm_x4(xlo_b + off, alo[mt][0], alo[mt][1], alo[mt][2], alo[mt][3]);
            }
            uint32_t bhi[NT][2];
            uint32_t blo[NT][2];
#pragma unroll
            for (int np = 0; np < NT / 2; np++) {
                int r = ks * 16 + (lane & 15);
                int c = warp_n * WN + np * 16 + (lane >> 4) * 8;
                uint32_t off = (uint32_t)(r * WS + c) * 2;
                ldsm_x4_t(whi_b + off, bhi[2 * np][0], bhi[2 * np][1],
                          bhi[2 * np + 1][0], bhi[2 * np + 1][1]);
                ldsm_x4_t(wlo_b + off, blo[2 * np][0], blo[2 * np][1],
                          blo[2 * np + 1][0], blo[2 * np + 1][1]);
            }
#pragma unroll
            for (int mt = 0; mt < MT; mt++)
#pragma unroll
                for (int nt = 0; nt < NT; nt++) {
                    mma_bf16(acc[mt][nt], ahi[mt], bhi[nt]);
                    mma_bf16(acc[mt][nt], ahi[mt], blo[nt]);
                    mma_bf16(acc[mt][nt], alo[mt], bhi[nt]);
                }
        }
        __syncthreads();
    }

    // ---- store fp32 + fp16 shadow ----
#pragma unroll
    for (int mt = 0; mt < MT; mt++) {
#pragma unroll
        for (int nt = 0; nt < NT; nt++) {
            int row = rowBase + warp_m * 32 + mt * 16 + (lane >> 2);
            int col = warp_n * WN + nt * 8 + (lane & 3) * 2;
            if (row < M) {
                *(float2*)(out + (size_t)row * Nout + col) =
                    make_float2(acc[mt][nt][0], acc[mt][nt][1]);
                *(__half2*)(out16 + (size_t)row * Nout + col) =
                    __floats2half2_rn(acc[mt][nt][0], acc[mt][nt][1]);
            }
            if (row + 8 < M) {
                *(float2*)(out + (size_t)(row + 8) * Nout + col) =
                    make_float2(acc[mt][nt][2], acc[mt][nt][3]);
                *(__half2*)(out16 + (size_t)(row + 8) * Nout + col) =
                    __floats2half2_rn(acc[mt][nt][2], acc[mt][nt][3]);
            }
        }
    }
}

// ---------------------------------------------------------------------------
// Fused aggregation: out[d] = act( dinv[d]^2*H[d] + sum_e w[e]*H16[src[e]] + b )
// Self term from exact fp32 H; edge gathers from fp16 shadow (half traffic).
// One warp per node. No atomics.
// ---------------------------------------------------------------------------
template <int F, int ACT>
__global__ void agg_fused(const float* __restrict__ H,
                          const __half* __restrict__ H16,
                          const int* __restrict__ rowstart,
                          const int* __restrict__ deg,
                          const int* __restrict__ csr_src,
                          const float* __restrict__ csr_w,
                          const float* __restrict__ dinv,
                          const float* __restrict__ bias,
                          float* __restrict__ out, int M) {
    constexpr int V = F / 32;   // floats per lane (4 or 2)
    int warp = (blockIdx.x * blockDim.x + threadIdx.x) >> 5;
    if (warp >= M) return;
    int lane = threadIdx.x & 31;

    float acc[V];
    {
        float dv = dinv[warp];
        float s = dv * dv;
        if (V == 4) {
            float4 v = *(const float4*)(H + (size_t)warp * F + lane * 4);
            acc[0] = s * v.x; acc[1] = s * v.y; acc[2] = s * v.z; acc[3] = s * v.w;
        } else {
            float2 v = *(const float2*)(H + (size_t)warp * F + lane * 2);
            acc[0] = s * v.x; acc[1] = s * v.y;
        }
    }

    int beg = rowstart[warp];
    int n = deg[warp];
    int j = 0;
    for (; j + 2 <= n; j += 2) {
        int s0 = csr_src[beg + j];
        int s1 = csr_src[beg + j + 1];
        float w0 = csr_w[beg + j];
        float w1 = csr_w[beg + j + 1];
        if (V == 4) {
            uint2 r0 = *(const uint2*)(H16 + (size_t)s0 * F + lane * 4);
            uint2 r1 = *(const uint2*)(H16 + (size_t)s1 * F + lane * 4);
            float2 a0 = __half22float2(*(__half2*)&r0.x);
            float2 b0 = __half22float2(*(__half2*)&r0.y);
            float2 a1 = __half22float2(*(__half2*)&r1.x);
            float2 b1 = __half22float2(*(__half2*)&r1.y);
            acc[0] = fmaf(w0, a0.x, acc[0]); acc[1] = fmaf(w0, a0.y, acc[1]);
            acc[2] = fmaf(w0, b0.x, acc[2]); acc[3] = fmaf(w0, b0.y, acc[3]);
            acc[0] = fmaf(w1, a1.x, acc[0]); acc[1] = fmaf(w1, a1.y, acc[1]);
            acc[2] = fmaf(w1, b1.x, acc[2]); acc[3] = fmaf(w1, b1.y, acc[3]);
        } else {
            uint32_t r0 = *(const uint32_t*)(H16 + (size_t)s0 * F + lane * 2);
            uint32_t r1 = *(const uint32_t*)(H16 + (size_t)s1 * F + lane * 2);
            float2 a0 = __half22float2(*(__half2*)&r0);
            float2 a1 = __half22float2(*(__half2*)&r1);
            acc[0] = fmaf(w0, a0.x, acc[0]); acc[1] = fmaf(w0, a0.y, acc[1]);
            acc[0] = fmaf(w1, a1.x, acc[0]); acc[1] = fmaf(w1, a1.y, acc[1]);
        }
    }
    if (j < n) {
        int s0 = csr_src[beg + j];
        float w0 = csr_w[beg + j];
        if (V == 4) {
            uint2 r0 = *(const uint2*)(H16 + (size_t)s0 * F + lane * 4);
            float2 a0 = __half22float2(*(__half2*)&r0.x);
            float2 b0 = __half22float2(*(__half2*)&r0.y);
            acc[0] = fmaf(w0, a0.x, acc[0]); acc[1] = fmaf(w0, a0.y, acc[1]);
            acc[2] = fmaf(w0, b0.x, acc[2]); acc[3] = fmaf(w0, b0.y, acc[3]);
        } else {
            uint32_t r0 = *(const uint32_t*)(H16 + (size_t)s0 * F + lane * 2);
            float2 a0 = __half22float2(*(__half2*)&r0);
            acc[0] = fmaf(w0, a0.x, acc[0]); acc[1] = fmaf(w0, a0.y, acc[1]);
        }
    }

    if (V == 4) {
        float4 b = *(const float4*)(bias + lane * 4);
        acc[0] += b.x; acc[1] += b.y; acc[2] += b.z; acc[3] += b.w;
        if (ACT) {
            acc[0] = tanhf(acc[0]); acc[1] = tanhf(acc[1]);
            acc[2] = tanhf(acc[2]); acc[3] = tanhf(acc[3]);
        }
        *(float4*)(out + (size_t)warp * F + lane * 4) =
            make_float4(acc[0], acc[1], acc[2], acc[3]);
    } else {
        float2 b = *(const float2*)(bias + lane * 2);
        acc[0] += b.x; acc[1] += b.y;
        if (ACT) { acc[0] = tanhf(acc[0]); acc[1] = tanhf(acc[1]); }
        *(float2*)(out + (size_t)warp * F + lane * 2) = make_float2(acc[0], acc[1]);
    }
}

// ---------------------------------------------------------------------------
// Host side
// ---------------------------------------------------------------------------
extern "C" void kernel_launch(void* const* d_in, const int* in_sizes, int n_in,
                              void* d_out, int out_size) {
    const float* feat = (const float*)d_in[0];   // [N,128] f32
    const float* cond = (const float*)d_in[1];   // [N,32]  f32
    const int*   ei   = (const int*)d_in[2];     // [2,E] int32
    const float* We1 = (const float*)d_in[3];
    const float* be1 = (const float*)d_in[4];
    const float* We2 = (const float*)d_in[5];
    const float* be2 = (const float*)d_in[6];
    const float* We3 = (const float*)d_in[7];
    const float* be3 = (const float*)d_in[8];
    const float* Wd1 = (const float*)d_in[9];
    const float* bd1 = (const float*)d_in[10];
    const float* Wd2 = (const float*)d_in[11];
    const float* bd2 = (const float*)d_in[12];
    const float* Wd3 = (const float*)d_in[13];
    const float* bd3 = (const float*)d_in[14];

    const int N = in_sizes[0] / 128;
    const int E = in_sizes[2] / 2;
    const int* src = ei;
    const int* dst = ei + E;
    float* out = (float*)d_out;

    float *dinv, *buf1, *buf2, *csr_w;
    __half* h16;
    int *deg, *rowstart, *cursor, *csr_src, *gcur;
    cudaGetSymbolAddress((void**)&dinv, g_dinv);
    cudaGetSymbolAddress((void**)&deg, g_deg);
    cudaGetSymbolAddress((void**)&rowstart, g_rowstart);
    cudaGetSymbolAddress((void**)&cursor, g_cursor);
    cudaGetSymbolAddress((void**)&csr_src, g_csr_src);
    cudaGetSymbolAddress((void**)&csr_w, g_csr_w);
    cudaGetSymbolAddress((void**)&buf1, g_buf1);
    cudaGetSymbolAddress((void**)&buf2, g_buf2);
    cudaGetSymbolAddress((void**)&h16, g_h16);
    cudaGetSymbolAddress((void**)&gcur, g_gcur);

    // ---- CSR build (once per launch) ----
    reset_counters<<<cdiv(N, 256), 256>>>(deg, gcur, N);
    deg_count<<<cdiv(E, 256), 256>>>(dst, deg, E);
    dinv_compute<<<cdiv(N, 256), 256>>>(deg, dinv, N);
    assign_rows<<<cdiv(N, 256), 256>>>(deg, rowstart, cursor, gcur, N);
    csr_fill<<<cdiv(E, 256), 256>>>(src, dst, dinv, cursor, csr_src, csr_w, E);

    dim3 gB(1, cdiv(N, 128));
    const int aggBlocks = cdiv(N * 32, 256);

    // encoder layer 1: [feat|cond] (K=160) -> 128, tanh
    gemm_mma<128><<<gB, 256>>>(feat, 128, cond, 32, We1, buf1, h16, N, 128);
    agg_fused<128, 1><<<aggBlocks, 256>>>(buf1, h16, rowstart, deg, csr_src, csr_w, dinv, be1, buf2, N);

    // encoder layer 2: 128 -> 128, tanh
    gemm_mma<128><<<gB, 256>>>(buf2, 128, nullptr, 0, We2, buf1, h16, N, 128);
    agg_fused<128, 1><<<aggBlocks, 256>>>(buf1, h16, rowstart, deg, csr_src, csr_w, dinv, be2, buf2, N);

    // encoder layer 3: 128 -> 64 (z), no activation
    gemm_mma<64><<<gB, 256>>>(buf2, 128, nullptr, 0, We3, buf1, h16, N, 64);
    agg_fused<64, 0><<<aggBlocks, 256>>>(buf1, h16, rowstart, deg, csr_src, csr_w, dinv, be3, buf2, N);

    // decoder layer 1: [z|cond] (K=96) -> 128, tanh
    gemm_mma<128><<<gB, 256>>>(buf2, 64, cond, 32, Wd1, buf1, h16, N, 128);
    agg_fused<128, 1><<<aggBlocks, 256>>>(buf1, h16, rowstart, deg, csr_src, csr_w, dinv, bd1, buf2, N);

    // decoder layer 2: 128 -> 128, tanh
    gemm_mma<128><<<gB, 256>>>(buf2, 128, nullptr, 0, Wd2, buf1, h16, N, 128);
    agg_fused<128, 1><<<aggBlocks, 256>>>(buf1, h16, rowstart, deg, csr_src, csr_w, dinv, bd2, buf2, N);

    // decoder layer 3: 128 -> 128, no activation, write to d_out
    gemm_mma<128><<<gB, 256>>>(buf2, 128, nullptr, 0, Wd3, buf1, h16, N, 128);
    agg_fused<128, 0><<<aggBlocks, 256>>>(buf1, h16, rowstart, deg, csr_src, csr_w, dinv, bd3, out, N);
}